// round 3
// baseline (speedup 1.0000x reference)
#include <cuda_runtime.h>

#define NN 100000
#define NE 1600000
#define FD 128

// ---- scratch (static device allocations; no runtime alloc allowed) ----
static __device__ float g_h[(size_t)NN * FD];     // scaled node features (reused both layers)
static __device__ float g_agg1[(size_t)NN * FD];  // layer-1 aggregation
static __device__ float g_agg2[(size_t)NN * FD];  // layer-2 aggregation
static __device__ float g_nsrc[NN];               // deg_out -> rsqrt
static __device__ float g_ndst[NN];               // deg_in  -> rsqrt
static __device__ float g_a[NN];                  // dot(h2, Wp[:128])
static __device__ float g_c[NN];                  // dot(h2, Wp[128:])

// ---- degree counting ----
__global__ void degree_k(const int* __restrict__ src, const int* __restrict__ dst) {
    int e = blockIdx.x * blockDim.x + threadIdx.x;
    if (e < NE) {
        atomicAdd(&g_nsrc[src[e]], 1.0f);
        atomicAdd(&g_ndst[dst[e]], 1.0f);
    }
}

__global__ void norm_k() {
    int i = blockIdx.x * blockDim.x + threadIdx.x;
    if (i < NN) {
        g_nsrc[i] = rsqrtf(fmaxf(g_nsrc[i], 1.0f));
        g_ndst[i] = rsqrtf(fmaxf(g_ndst[i], 1.0f));
    }
}

// ---- GEMM: out[i][:] = norm_src[i] * (in_row(i) @ W) ----
// FUSED=false: in_row(i) = in[i][:]                      (layer 1, in = x)
// FUSED=true : in_row(i) = relu(in[i][:]*norm_dst[i]+b)  (layer 2, in = agg1)
// Block: 256 threads, 64 rows. W read through L1 (__ldg), rows staged in smem.
// Each thread owns an 8-row x 4-col register tile -> FMA-pipe bound.
template <bool FUSED>
__global__ __launch_bounds__(256) void gemm_k(const float* __restrict__ in,
                                              const float* __restrict__ W,
                                              const float* __restrict__ bias,
                                              float* __restrict__ out) {
    __shared__ float sIn[64 * FD];
    const int tid = threadIdx.x;
    const int row0 = blockIdx.x * 64;

    // cooperative load of 64 input rows (fusing relu/norm/bias for layer 2)
    for (int i = tid; i < 64 * (FD / 4); i += 256) {
        int r = i >> 5;
        int cq = i & 31;
        int gr = row0 + r;
        float4 v = make_float4(0.f, 0.f, 0.f, 0.f);
        if (gr < NN) {
            v = *reinterpret_cast<const float4*>(in + (size_t)gr * FD + cq * 4);
            if (FUSED) {
                float nd = g_ndst[gr];
                float4 b = __ldg(reinterpret_cast<const float4*>(bias + cq * 4));
                v.x = fmaxf(fmaf(v.x, nd, b.x), 0.f);
                v.y = fmaxf(fmaf(v.y, nd, b.y), 0.f);
                v.z = fmaxf(fmaf(v.z, nd, b.z), 0.f);
                v.w = fmaxf(fmaf(v.w, nd, b.w), 0.f);
            }
        }
        *reinterpret_cast<float4*>(&sIn[r * FD + cq * 4]) = v;
    }
    __syncthreads();

    const int lane = tid & 31;
    const int wid = tid >> 5;
    const int c0 = lane * 4;       // 4 output columns per lane
    const int rbase = wid * 8;     // 8 rows per warp

    float acc[8][4];
#pragma unroll
    for (int r = 0; r < 8; r++) {
        acc[r][0] = acc[r][1] = acc[r][2] = acc[r][3] = 0.f;
    }

#pragma unroll 4
    for (int k = 0; k < FD; k++) {
        float4 w4 = __ldg(reinterpret_cast<const float4*>(W + k * FD + c0));
#pragma unroll
        for (int r = 0; r < 8; r++) {
            float a = sIn[(rbase + r) * FD + k];  // warp-broadcast LDS
            acc[r][0] = fmaf(a, w4.x, acc[r][0]);
            acc[r][1] = fmaf(a, w4.y, acc[r][1]);
            acc[r][2] = fmaf(a, w4.z, acc[r][2]);
            acc[r][3] = fmaf(a, w4.w, acc[r][3]);
        }
    }

#pragma unroll
    for (int r = 0; r < 8; r++) {
        int gr = row0 + rbase + r;
        if (gr < NN) {
            float ns = g_nsrc[gr];  // fold source-side norm into stored features
            float4 o = make_float4(acc[r][0] * ns, acc[r][1] * ns,
                                   acc[r][2] * ns, acc[r][3] * ns);
            *reinterpret_cast<float4*>(out + (size_t)gr * FD + c0) = o;
        }
    }
}

// ---- edge scatter: agg[dst] += h[src], one warp per edge, 16B vector RED ----
__global__ __launch_bounds__(256) void scatter_k(const int* __restrict__ src,
                                                 const int* __restrict__ dst,
                                                 const float* __restrict__ h,
                                                 float* __restrict__ agg) {
    int t = blockIdx.x * 256 + threadIdx.x;
    int e = t >> 5;
    if (e >= NE) return;
    int lane = t & 31;
    int s = __ldg(src + e);
    int d = __ldg(dst + e);
    float4 v = *reinterpret_cast<const float4*>(h + (size_t)s * FD + lane * 4);
    float* p = agg + (size_t)d * FD + lane * 4;
    asm volatile("red.global.add.v4.f32 [%0], {%1, %2, %3, %4};"
                 :: "l"(p), "f"(v.x), "f"(v.y), "f"(v.z), "f"(v.w)
                 : "memory");
}

// ---- per-node link-predictor projection: a[i], c[i] (warp per node) ----
__global__ void nodescore_k(const float* __restrict__ Wp, const float* __restrict__ b2) {
    int t = blockIdx.x * blockDim.x + threadIdx.x;
    int i = t >> 5;
    if (i >= NN) return;
    int lane = t & 31;
    float4 agg = *reinterpret_cast<const float4*>(g_agg2 + (size_t)i * FD + lane * 4);
    float nd = g_ndst[i];
    float4 b  = __ldg(reinterpret_cast<const float4*>(b2 + lane * 4));
    float4 w1 = __ldg(reinterpret_cast<const float4*>(Wp + lane * 4));
    float4 w2 = __ldg(reinterpret_cast<const float4*>(Wp + FD + lane * 4));
    float hx = fmaf(agg.x, nd, b.x);
    float hy = fmaf(agg.y, nd, b.y);
    float hz = fmaf(agg.z, nd, b.z);
    float hw = fmaf(agg.w, nd, b.w);
    float av = hx * w1.x + hy * w1.y + hz * w1.z + hw * w1.w;
    float cv = hx * w2.x + hy * w2.y + hz * w2.z + hw * w2.w;
#pragma unroll
    for (int off = 16; off > 0; off >>= 1) {
        av += __shfl_xor_sync(0xffffffffu, av, off);
        cv += __shfl_xor_sync(0xffffffffu, cv, off);
    }
    if (lane == 0) { g_a[i] = av; g_c[i] = cv; }
}

// ---- final per-edge score: sigmoid(a[src] + c[dst] + bp) ----
__global__ void edgescore_k(const int* __restrict__ src, const int* __restrict__ dst,
                            const float* __restrict__ bp, float* __restrict__ out) {
    int e = blockIdx.x * blockDim.x + threadIdx.x;
    if (e < NE) {
        float z = g_a[__ldg(src + e)] + g_c[__ldg(dst + e)] + __ldg(bp);
        out[e] = 1.0f / (1.0f + expf(-z));
    }
}

extern "C" void kernel_launch(void* const* d_in, const int* in_sizes, int n_in,
                              void* d_out, int out_size) {
    (void)in_sizes; (void)n_in; (void)out_size;
    const float* x  = (const float*)d_in[0];
    const float* W1 = (const float*)d_in[1];
    const float* b1 = (const float*)d_in[2];
    const float* W2 = (const float*)d_in[3];
    const float* b2 = (const float*)d_in[4];
    const float* Wp = (const float*)d_in[5];
    const float* bp = (const float*)d_in[6];
    const int* src  = (const int*)d_in[7];
    const int* dst  = (const int*)d_in[8];
    float* out = (float*)d_out;

    void *p_h, *p_a1, *p_a2, *p_ns, *p_nd;
    cudaGetSymbolAddress(&p_h,  g_h);
    cudaGetSymbolAddress(&p_a1, g_agg1);
    cudaGetSymbolAddress(&p_a2, g_agg2);
    cudaGetSymbolAddress(&p_ns, g_nsrc);
    cudaGetSymbolAddress(&p_nd, g_ndst);

    cudaMemsetAsync(p_a1, 0, sizeof(float) * (size_t)NN * FD);
    cudaMemsetAsync(p_a2, 0, sizeof(float) * (size_t)NN * FD);
    cudaMemsetAsync(p_ns, 0, sizeof(float) * NN);
    cudaMemsetAsync(p_nd, 0, sizeof(float) * NN);

    degree_k<<<(NE + 255) / 256, 256>>>(src, dst);
    norm_k<<<(NN + 255) / 256, 256>>>();

    // Layer 1: h = (x @ W1) * norm_src
    gemm_k<false><<<(NN + 63) / 64, 256>>>(x, W1, nullptr, (float*)p_h);
    // agg1[dst] += h[src]
    scatter_k<<<(NE * 32) / 256, 256>>>(src, dst, (const float*)p_h, (float*)p_a1);

    // Layer 2: h = (relu(agg1*norm_dst + b1) @ W2) * norm_src   (fused load)
    gemm_k<true><<<(NN + 63) / 64, 256>>>((const float*)p_a1, W2, b1, (float*)p_h);
    // agg2[dst] += h[src]
    scatter_k<<<(NE * 32) / 256, 256>>>(src, dst, (const float*)p_h, (float*)p_a2);

    // Per-node projections of the link predictor, then per-edge sigmoid
    nodescore_k<<<(NN * 32 + 255) / 256, 256>>>(Wp, b2);
    edgescore_k<<<(NE + 255) / 256, 256>>>(src, dst, bp, out);
}

// round 4
// speedup vs baseline: 1.8063x; 1.8063x over previous
#include <cuda_runtime.h>

#define NN 100000
#define NE 1600000
#define FD 128
#define NB 391          // ceil(NN / 256)

// ---- scratch (static device arrays; no runtime alloc allowed) ----
static __device__ float g_h[(size_t)NN * FD];   // post-GEMM node features (both layers)
static __device__ float g_z[(size_t)NN * FD];   // relu(agg1*nd + b1) = GEMM2 input
static __device__ int   g_degout[NN];
static __device__ int   g_degin[NN];
static __device__ float g_nsrc[NN];
static __device__ float g_ndst[NN];
static __device__ int   g_rowptr[NN + 1];
static __device__ int   g_cursor[NN];
static __device__ int   g_csr[NE];              // src ids bucketed by dst
static __device__ int   g_bsum[512];
static __device__ float g_a[NN];                // dot(h2, Wp[:128])
static __device__ float g_c[NN];                // dot(h2, Wp[128:])

// ---- degree counting (ints) ----
__global__ void count_k(const int* __restrict__ src, const int* __restrict__ dst) {
    int e = blockIdx.x * blockDim.x + threadIdx.x;
    if (e < NE) {
        atomicAdd(&g_degout[src[e]], 1);
        atomicAdd(&g_degin[dst[e]], 1);
    }
}

__global__ void norm_k() {
    int i = blockIdx.x * blockDim.x + threadIdx.x;
    if (i < NN) {
        g_nsrc[i] = rsqrtf(fmaxf((float)g_degout[i], 1.0f));
        g_ndst[i] = rsqrtf(fmaxf((float)g_degin[i], 1.0f));
    }
}

// ---- CSR build: block sums -> scan of block sums -> row_ptr + cursor -> fill ----
__global__ void blocksum_k() {
    int i = blockIdx.x * 256 + threadIdx.x;
    int v = (i < NN) ? g_degin[i] : 0;
#pragma unroll
    for (int off = 16; off > 0; off >>= 1) v += __shfl_xor_sync(0xffffffffu, v, off);
    __shared__ int s[8];
    int lane = threadIdx.x & 31, wid = threadIdx.x >> 5;
    if (lane == 0) s[wid] = v;
    __syncthreads();
    if (threadIdx.x == 0) {
        int t = 0;
#pragma unroll
        for (int w = 0; w < 8; w++) t += s[w];
        g_bsum[blockIdx.x] = t;
    }
}

__global__ void scanbsum_k() {   // single block, exclusive scan of NB block sums
    __shared__ int sh[512];
    int t = threadIdx.x;
    int v = (t < NB) ? g_bsum[t] : 0;
    sh[t] = v;
    __syncthreads();
    for (int off = 1; off < 512; off <<= 1) {
        int a = (t >= off) ? sh[t - off] : 0;
        __syncthreads();
        sh[t] += a;
        __syncthreads();
    }
    if (t < NB) g_bsum[t] = sh[t] - v;   // exclusive
}

__global__ void rowptr_k() {
    int i = blockIdx.x * 256 + threadIdx.x;
    int lane = threadIdx.x & 31, wid = threadIdx.x >> 5;
    int v = (i < NN) ? g_degin[i] : 0;
    int incl = v;
#pragma unroll
    for (int off = 1; off < 32; off <<= 1) {
        int n = __shfl_up_sync(0xffffffffu, incl, off);
        if (lane >= off) incl += n;
    }
    __shared__ int ws[8];
    if (lane == 31) ws[wid] = incl;
    __syncthreads();
    if (threadIdx.x == 0) {
        int run = 0;
#pragma unroll
        for (int w = 0; w < 8; w++) { int t = ws[w]; ws[w] = run; run += t; }
    }
    __syncthreads();
    int excl = incl - v + ws[wid] + g_bsum[blockIdx.x];
    if (i < NN) {
        g_rowptr[i] = excl;
        g_cursor[i] = excl;
        if (i == NN - 1) g_rowptr[NN] = excl + v;
    }
}

__global__ void fill_k(const int* __restrict__ src, const int* __restrict__ dst) {
    int e = blockIdx.x * blockDim.x + threadIdx.x;
    if (e < NE) {
        int d = dst[e];
        int pos = atomicAdd(&g_cursor[d], 1);
        g_csr[pos] = src[e];
    }
}

// ---- GEMM: out[i][:] = norm_src[i] * (in[i][:] @ W) ----
__global__ __launch_bounds__(256) void gemm_k(const float* __restrict__ in,
                                              const float* __restrict__ W,
                                              float* __restrict__ out) {
    __shared__ float sIn[64 * FD];
    const int tid = threadIdx.x;
    const int row0 = blockIdx.x * 64;

    for (int i = tid; i < 64 * (FD / 4); i += 256) {
        int r = i >> 5;
        int cq = i & 31;
        int gr = row0 + r;
        float4 v = make_float4(0.f, 0.f, 0.f, 0.f);
        if (gr < NN) v = *reinterpret_cast<const float4*>(in + (size_t)gr * FD + cq * 4);
        *reinterpret_cast<float4*>(&sIn[r * FD + cq * 4]) = v;
    }
    __syncthreads();

    const int lane = tid & 31;
    const int wid = tid >> 5;
    const int c0 = lane * 4;
    const int rbase = wid * 8;

    float acc[8][4];
#pragma unroll
    for (int r = 0; r < 8; r++)
        acc[r][0] = acc[r][1] = acc[r][2] = acc[r][3] = 0.f;

#pragma unroll 4
    for (int k = 0; k < FD; k++) {
        float4 w4 = __ldg(reinterpret_cast<const float4*>(W + k * FD + c0));
#pragma unroll
        for (int r = 0; r < 8; r++) {
            float a = sIn[(rbase + r) * FD + k];
            acc[r][0] = fmaf(a, w4.x, acc[r][0]);
            acc[r][1] = fmaf(a, w4.y, acc[r][1]);
            acc[r][2] = fmaf(a, w4.z, acc[r][2]);
            acc[r][3] = fmaf(a, w4.w, acc[r][3]);
        }
    }

#pragma unroll
    for (int r = 0; r < 8; r++) {
        int gr = row0 + rbase + r;
        if (gr < NN) {
            float ns = g_nsrc[gr];
            float4 o = make_float4(acc[r][0] * ns, acc[r][1] * ns,
                                   acc[r][2] * ns, acc[r][3] * ns);
            *reinterpret_cast<float4*>(out + (size_t)gr * FD + c0) = o;
        }
    }
}

// ---- warp-per-node CSR accumulate, unroll-4 for MLP ----
__device__ __forceinline__ float4 csr_accum(int node, const float* __restrict__ h, int lane) {
    int beg = g_rowptr[node];
    int end = g_rowptr[node + 1];
    float4 acc = make_float4(0.f, 0.f, 0.f, 0.f);
    int j = beg;
    for (; j + 4 <= end; j += 4) {
        int s0 = __ldg(g_csr + j);
        int s1 = __ldg(g_csr + j + 1);
        int s2 = __ldg(g_csr + j + 2);
        int s3 = __ldg(g_csr + j + 3);
        float4 v0 = *reinterpret_cast<const float4*>(h + (size_t)s0 * FD + lane * 4);
        float4 v1 = *reinterpret_cast<const float4*>(h + (size_t)s1 * FD + lane * 4);
        float4 v2 = *reinterpret_cast<const float4*>(h + (size_t)s2 * FD + lane * 4);
        float4 v3 = *reinterpret_cast<const float4*>(h + (size_t)s3 * FD + lane * 4);
        acc.x += (v0.x + v1.x) + (v2.x + v3.x);
        acc.y += (v0.y + v1.y) + (v2.y + v3.y);
        acc.z += (v0.z + v1.z) + (v2.z + v3.z);
        acc.w += (v0.w + v1.w) + (v2.w + v3.w);
    }
    for (; j < end; j++) {
        int s = __ldg(g_csr + j);
        float4 v = *reinterpret_cast<const float4*>(h + (size_t)s * FD + lane * 4);
        acc.x += v.x; acc.y += v.y; acc.z += v.z; acc.w += v.w;
    }
    return acc;
}

// ---- layer 1 aggregate, fused epilogue: z = relu(agg*nd + b1) ----
__global__ __launch_bounds__(256) void gather1_k(const float* __restrict__ b1) {
    int w = (blockIdx.x * 256 + threadIdx.x) >> 5;
    if (w >= NN) return;
    int lane = threadIdx.x & 31;
    float4 acc = csr_accum(w, g_h, lane);
    float nd = g_ndst[w];
    float4 b = __ldg(reinterpret_cast<const float4*>(b1 + lane * 4));
    float4 o;
    o.x = fmaxf(fmaf(acc.x, nd, b.x), 0.f);
    o.y = fmaxf(fmaf(acc.y, nd, b.y), 0.f);
    o.z = fmaxf(fmaf(acc.z, nd, b.z), 0.f);
    o.w = fmaxf(fmaf(acc.w, nd, b.w), 0.f);
    *reinterpret_cast<float4*>(g_z + (size_t)w * FD + lane * 4) = o;
}

// ---- layer 2 aggregate, fused link-predictor projection: a[i], c[i] ----
__global__ __launch_bounds__(256) void gather2_k(const float* __restrict__ b2,
                                                 const float* __restrict__ Wp) {
    int w = (blockIdx.x * 256 + threadIdx.x) >> 5;
    if (w >= NN) return;
    int lane = threadIdx.x & 31;
    float4 acc = csr_accum(w, g_h, lane);
    float nd = g_ndst[w];
    float4 b  = __ldg(reinterpret_cast<const float4*>(b2 + lane * 4));
    float4 w1 = __ldg(reinterpret_cast<const float4*>(Wp + lane * 4));
    float4 w2 = __ldg(reinterpret_cast<const float4*>(Wp + FD + lane * 4));
    float hx = fmaf(acc.x, nd, b.x);
    float hy = fmaf(acc.y, nd, b.y);
    float hz = fmaf(acc.z, nd, b.z);
    float hw = fmaf(acc.w, nd, b.w);
    float av = hx * w1.x + hy * w1.y + hz * w1.z + hw * w1.w;
    float cv = hx * w2.x + hy * w2.y + hz * w2.z + hw * w2.w;
#pragma unroll
    for (int off = 16; off > 0; off >>= 1) {
        av += __shfl_xor_sync(0xffffffffu, av, off);
        cv += __shfl_xor_sync(0xffffffffu, cv, off);
    }
    if (lane == 0) { g_a[w] = av; g_c[w] = cv; }
}

// ---- final per-edge score: sigmoid(a[src] + c[dst] + bp) ----
__global__ void edgescore_k(const int* __restrict__ src, const int* __restrict__ dst,
                            const float* __restrict__ bp, float* __restrict__ out) {
    int e = blockIdx.x * blockDim.x + threadIdx.x;
    if (e < NE) {
        float z = g_a[__ldg(src + e)] + g_c[__ldg(dst + e)] + __ldg(bp);
        out[e] = 1.0f / (1.0f + expf(-z));
    }
}

extern "C" void kernel_launch(void* const* d_in, const int* in_sizes, int n_in,
                              void* d_out, int out_size) {
    (void)in_sizes; (void)n_in; (void)out_size;
    const float* x  = (const float*)d_in[0];
    const float* W1 = (const float*)d_in[1];
    const float* b1 = (const float*)d_in[2];
    const float* W2 = (const float*)d_in[3];
    const float* b2 = (const float*)d_in[4];
    const float* Wp = (const float*)d_in[5];
    const float* bp = (const float*)d_in[6];
    const int* src  = (const int*)d_in[7];
    const int* dst  = (const int*)d_in[8];
    float* out = (float*)d_out;

    void *p_h, *p_z, *p_di, *p_do;
    cudaGetSymbolAddress(&p_h, g_h);
    cudaGetSymbolAddress(&p_z, g_z);
    cudaGetSymbolAddress(&p_di, g_degin);
    cudaGetSymbolAddress(&p_do, g_degout);

    cudaMemsetAsync(p_di, 0, sizeof(int) * NN);
    cudaMemsetAsync(p_do, 0, sizeof(int) * NN);

    // degrees + norms + CSR (dst-bucketed) build
    count_k<<<(NE + 255) / 256, 256>>>(src, dst);
    norm_k<<<(NN + 255) / 256, 256>>>();
    blocksum_k<<<NB, 256>>>();
    scanbsum_k<<<1, 512>>>();
    rowptr_k<<<NB, 256>>>();
    fill_k<<<(NE + 255) / 256, 256>>>(src, dst);

    // Layer 1: h = (x @ W1) * norm_src ; z = relu(agg1 * norm_dst + b1)
    gemm_k<<<(NN + 63) / 64, 256>>>(x, W1, (float*)p_h);
    gather1_k<<<(NN * 32 + 255) / 256, 256>>>(b1);

    // Layer 2: h = (z @ W2) * norm_src ; fused gather -> per-node a, c
    gemm_k<<<(NN + 63) / 64, 256>>>((const float*)p_z, W2, (float*)p_h);
    gather2_k<<<(NN * 32 + 255) / 256, 256>>>(b2, Wp);

    // Per-edge score
    edgescore_k<<<(NE + 255) / 256, 256>>>(src, dst, bp, out);
}

// round 7
// speedup vs baseline: 1.9018x; 1.0529x over previous
#include <cuda_runtime.h>
#include <cuda_fp16.h>

#define NN 100000
#define NE 1600000
#define FD 128
#define NB 391          // ceil(NN / 256)

typedef unsigned long long ull;

// ---- scratch (static device arrays; no runtime alloc allowed) ----
static __device__ __half g_hh[(size_t)NN * FD];   // post-GEMM node features (fp16, both layers)
static __device__ float  g_z[(size_t)NN * FD];    // relu(agg1*nd + b1) = GEMM2 input (fp32)
static __device__ float2 g_Wpair[64 * FD];        // W packed as {W[2k][c], W[2k+1][c]}
static __device__ int    g_degout[NN];
static __device__ int    g_degin[NN];
static __device__ float  g_nsrc[NN];
static __device__ float  g_ndst[NN];
static __device__ int    g_rowptr[NN + 1];
static __device__ int    g_cursor[NN];
static __device__ int    g_csr[NE];               // src ids bucketed by dst
static __device__ int    g_bsum[512];
static __device__ float  g_a[NN];                 // dot(h2, Wp[:128])
static __device__ float  g_c[NN];                 // dot(h2, Wp[128:])

// ---- degree counting ----
__global__ void count_k(const int* __restrict__ src, const int* __restrict__ dst) {
    int e = blockIdx.x * blockDim.x + threadIdx.x;
    if (e < NE) {
        atomicAdd(&g_degout[src[e]], 1);
        atomicAdd(&g_degin[dst[e]], 1);
    }
}

__global__ void norm_k() {
    int i = blockIdx.x * blockDim.x + threadIdx.x;
    if (i < NN) {
        g_nsrc[i] = rsqrtf(fmaxf((float)g_degout[i], 1.0f));
        g_ndst[i] = rsqrtf(fmaxf((float)g_degin[i], 1.0f));
    }
}

// ---- CSR build ----
__global__ void blocksum_k() {
    int i = blockIdx.x * 256 + threadIdx.x;
    int v = (i < NN) ? g_degin[i] : 0;
#pragma unroll
    for (int off = 16; off > 0; off >>= 1) v += __shfl_xor_sync(0xffffffffu, v, off);
    __shared__ int s[8];
    int lane = threadIdx.x & 31, wid = threadIdx.x >> 5;
    if (lane == 0) s[wid] = v;
    __syncthreads();
    if (threadIdx.x == 0) {
        int t = 0;
#pragma unroll
        for (int w = 0; w < 8; w++) t += s[w];
        g_bsum[blockIdx.x] = t;
    }
}

__global__ void scanbsum_k() {   // single block, exclusive scan of NB block sums
    __shared__ int sh[512];
    int t = threadIdx.x;
    int v = (t < NB) ? g_bsum[t] : 0;
    sh[t] = v;
    __syncthreads();
    for (int off = 1; off < 512; off <<= 1) {
        int a = (t >= off) ? sh[t - off] : 0;
        __syncthreads();
        sh[t] += a;
        __syncthreads();
    }
    if (t < NB) g_bsum[t] = sh[t] - v;   // exclusive
}

__global__ void rowptr_k() {
    int i = blockIdx.x * 256 + threadIdx.x;
    int lane = threadIdx.x & 31, wid = threadIdx.x >> 5;
    int v = (i < NN) ? g_degin[i] : 0;
    int incl = v;
#pragma unroll
    for (int off = 1; off < 32; off <<= 1) {
        int n = __shfl_up_sync(0xffffffffu, incl, off);
        if (lane >= off) incl += n;
    }
    __shared__ int ws[8];
    if (lane == 31) ws[wid] = incl;
    __syncthreads();
    if (threadIdx.x == 0) {
        int run = 0;
#pragma unroll
        for (int w = 0; w < 8; w++) { int t = ws[w]; ws[w] = run; run += t; }
    }
    __syncthreads();
    int excl = incl - v + ws[wid] + g_bsum[blockIdx.x];
    if (i < NN) {
        g_rowptr[i] = excl;
        g_cursor[i] = excl;
        if (i == NN - 1) g_rowptr[NN] = excl + v;
    }
}

__global__ void fill_k(const int* __restrict__ src, const int* __restrict__ dst) {
    int e = blockIdx.x * blockDim.x + threadIdx.x;
    if (e < NE) {
        int d = dst[e];
        int pos = atomicAdd(&g_cursor[d], 1);
        g_csr[pos] = src[e];
    }
}

// ---- pack W into k-pairs: g_Wpair[k2*FD + c] = {W[2k2][c], W[2k2+1][c]} ----
__global__ void packW_k(const float* __restrict__ W) {
    int i = blockIdx.x * blockDim.x + threadIdx.x;
    if (i < 64 * FD) {
        int k2 = i >> 7;
        int c = i & 127;
        g_Wpair[i] = make_float2(__ldg(W + (2 * k2) * FD + c),
                                 __ldg(W + (2 * k2 + 1) * FD + c));
    }
}

// ---- packed-fp32 FFMA2 helper ----
__device__ __forceinline__ void ffma2(ull& d, ull a, ull b) {
    asm("fma.rn.f32x2 %0, %1, %2, %0;" : "+l"(d) : "l"(a), "l"(b));
}

// ---- GEMM: out[i][:] = fp16( norm_src[i] * (in[i][:] @ W) ), FFMA2 k-split ----
// acc2[r][c] lanes = {sum over even k, sum over odd k}; a2 = contiguous LDS.64 broadcast.
__global__ __launch_bounds__(256) void gemm_k(const float* __restrict__ in,
                                              __half* __restrict__ out) {
    __shared__ float sIn[64 * FD];
    const int tid = threadIdx.x;
    const int row0 = blockIdx.x * 64;

    for (int i = tid; i < 64 * (FD / 4); i += 256) {
        int r = i >> 5;
        int cq = i & 31;
        int gr = row0 + r;
        float4 v = make_float4(0.f, 0.f, 0.f, 0.f);
        if (gr < NN) v = *reinterpret_cast<const float4*>(in + (size_t)gr * FD + cq * 4);
        *reinterpret_cast<float4*>(&sIn[r * FD + cq * 4]) = v;
    }
    __syncthreads();

    const int lane = tid & 31;
    const int wid = tid >> 5;
    const int c0 = lane * 4;       // 4 output columns per lane
    const int rbase = wid * 8;     // 8 rows per warp

    ull acc[8][4];
#pragma unroll
    for (int r = 0; r < 8; r++)
        acc[r][0] = acc[r][1] = acc[r][2] = acc[r][3] = 0ull;

#pragma unroll 2
    for (int k2 = 0; k2 < FD / 2; k2++) {
        // W pairs for this thread's 4 columns: 32 contiguous bytes -> 2x 16B loads
        ulonglong2 wA = __ldg(reinterpret_cast<const ulonglong2*>(g_Wpair + k2 * FD + c0));
        ulonglong2 wB = __ldg(reinterpret_cast<const ulonglong2*>(g_Wpair + k2 * FD + c0 + 2));
#pragma unroll
        for (int r = 0; r < 8; r++) {
            ull a2 = *reinterpret_cast<const ull*>(&sIn[(rbase + r) * FD + 2 * k2]);
            ffma2(acc[r][0], a2, wA.x);
            ffma2(acc[r][1], a2, wA.y);
            ffma2(acc[r][2], a2, wB.x);
            ffma2(acc[r][3], a2, wB.y);
        }
    }

#pragma unroll
    for (int r = 0; r < 8; r++) {
        int gr = row0 + rbase + r;
        if (gr < NN) {
            float ns = g_nsrc[gr];
            float2 f0 = *reinterpret_cast<float2*>(&acc[r][0]);
            float2 f1 = *reinterpret_cast<float2*>(&acc[r][1]);
            float2 f2 = *reinterpret_cast<float2*>(&acc[r][2]);
            float2 f3 = *reinterpret_cast<float2*>(&acc[r][3]);
            float v0 = (f0.x + f0.y) * ns;
            float v1 = (f1.x + f1.y) * ns;
            float v2 = (f2.x + f2.y) * ns;
            float v3 = (f3.x + f3.y) * ns;
            __half2 o01 = __floats2half2_rn(v0, v1);
            __half2 o23 = __floats2half2_rn(v2, v3);
            uint2 st;
            st.x = *reinterpret_cast<unsigned int*>(&o01);
            st.y = *reinterpret_cast<unsigned int*>(&o23);
            *reinterpret_cast<uint2*>(out + (size_t)gr * FD + c0) = st;
        }
    }
}

// ---- warp-per-node CSR accumulate over fp16 rows (fp32 accum), unroll-4 ----
__device__ __forceinline__ float4 csr_accum(int node, int lane) {
    int beg = g_rowptr[node];
    int end = g_rowptr[node + 1];
    float4 acc = make_float4(0.f, 0.f, 0.f, 0.f);
    int j = beg;
    for (; j + 4 <= end; j += 4) {
        int s0 = __ldg(g_csr + j);
        int s1 = __ldg(g_csr + j + 1);
        int s2 = __ldg(g_csr + j + 2);
        int s3 = __ldg(g_csr + j + 3);
        uint2 u0 = *reinterpret_cast<const uint2*>(g_hh + (size_t)s0 * FD + lane * 4);
        uint2 u1 = *reinterpret_cast<const uint2*>(g_hh + (size_t)s1 * FD + lane * 4);
        uint2 u2 = *reinterpret_cast<const uint2*>(g_hh + (size_t)s2 * FD + lane * 4);
        uint2 u3 = *reinterpret_cast<const uint2*>(g_hh + (size_t)s3 * FD + lane * 4);
        float2 a0 = __half22float2(*reinterpret_cast<__half2*>(&u0.x));
        float2 b0 = __half22float2(*reinterpret_cast<__half2*>(&u0.y));
        float2 a1 = __half22float2(*reinterpret_cast<__half2*>(&u1.x));
        float2 b1 = __half22float2(*reinterpret_cast<__half2*>(&u1.y));
        float2 a2 = __half22float2(*reinterpret_cast<__half2*>(&u2.x));
        float2 b2 = __half22float2(*reinterpret_cast<__half2*>(&u2.y));
        float2 a3 = __half22float2(*reinterpret_cast<__half2*>(&u3.x));
        float2 b3 = __half22float2(*reinterpret_cast<__half2*>(&u3.y));
        acc.x += (a0.x + a1.x) + (a2.x + a3.x);
        acc.y += (a0.y + a1.y) + (a2.y + a3.y);
        acc.z += (b0.x + b1.x) + (b2.x + b3.x);
        acc.w += (b0.y + b1.y) + (b2.y + b3.y);
    }
    for (; j < end; j++) {
        int s = __ldg(g_csr + j);
        uint2 u = *reinterpret_cast<const uint2*>(g_hh + (size_t)s * FD + lane * 4);
        float2 a = __half22float2(*reinterpret_cast<__half2*>(&u.x));
        float2 b = __half22float2(*reinterpret_cast<__half2*>(&u.y));
        acc.x += a.x; acc.y += a.y; acc.z += b.x; acc.w += b.y;
    }
    return acc;
}

// ---- layer 1 aggregate, fused epilogue: z = relu(agg*nd + b1) (fp32) ----
__global__ __launch_bounds__(256) void gather1_k(const float* __restrict__ b1) {
    int w = (blockIdx.x * 256 + threadIdx.x) >> 5;
    if (w >= NN) return;
    int lane = threadIdx.x & 31;
    float4 acc = csr_accum(w, lane);
    float nd = g_ndst[w];
    float4 b = __ldg(reinterpret_cast<const float4*>(b1 + lane * 4));
    float4 o;
    o.x = fmaxf(fmaf(acc.x, nd, b.x), 0.f);
    o.y = fmaxf(fmaf(acc.y, nd, b.y), 0.f);
    o.z = fmaxf(fmaf(acc.z, nd, b.z), 0.f);
    o.w = fmaxf(fmaf(acc.w, nd, b.w), 0.f);
    *reinterpret_cast<float4*>(g_z + (size_t)w * FD + lane * 4) = o;
}

// ---- layer 2 aggregate, fused link-predictor projection: a[i], c[i] ----
__global__ __launch_bounds__(256) void gather2_k(const float* __restrict__ b2,
                                                 const float* __restrict__ Wp) {
    int w = (blockIdx.x * 256 + threadIdx.x) >> 5;
    if (w >= NN) return;
    int lane = threadIdx.x & 31;
    float4 acc = csr_accum(w, lane);
    float nd = g_ndst[w];
    float4 b  = __ldg(reinterpret_cast<const float4*>(b2 + lane * 4));
    float4 w1 = __ldg(reinterpret_cast<const float4*>(Wp + lane * 4));
    float4 w2 = __ldg(reinterpret_cast<const float4*>(Wp + FD + lane * 4));
    float hx = fmaf(acc.x, nd, b.x);
    float hy = fmaf(acc.y, nd, b.y);
    float hz = fmaf(acc.z, nd, b.z);
    float hw = fmaf(acc.w, nd, b.w);
    float av = hx * w1.x + hy * w1.y + hz * w1.z + hw * w1.w;
    float cv = hx * w2.x + hy * w2.y + hz * w2.z + hw * w2.w;
#pragma unroll
    for (int off = 16; off > 0; off >>= 1) {
        av += __shfl_xor_sync(0xffffffffu, av, off);
        cv += __shfl_xor_sync(0xffffffffu, cv, off);
    }
    if (lane == 0) { g_a[w] = av; g_c[w] = cv; }
}

// ---- final per-edge score: sigmoid(a[src] + c[dst] + bp) ----
__global__ void edgescore_k(const int* __restrict__ src, const int* __restrict__ dst,
                            const float* __restrict__ bp, float* __restrict__ out) {
    int e = blockIdx.x * blockDim.x + threadIdx.x;
    if (e < NE) {
        float z = g_a[__ldg(src + e)] + g_c[__ldg(dst + e)] + __ldg(bp);
        out[e] = 1.0f / (1.0f + expf(-z));
    }
}

extern "C" void kernel_launch(void* const* d_in, const int* in_sizes, int n_in,
                              void* d_out, int out_size) {
    (void)in_sizes; (void)n_in; (void)out_size;
    const float* x  = (const float*)d_in[0];
    const float* W1 = (const float*)d_in[1];
    const float* b1 = (const float*)d_in[2];
    const float* W2 = (const float*)d_in[3];
    const float* b2 = (const float*)d_in[4];
    const float* Wp = (const float*)d_in[5];
    const float* bp = (const float*)d_in[6];
    const int* src  = (const int*)d_in[7];
    const int* dst  = (const int*)d_in[8];
    float* out = (float*)d_out;

    void *p_hh, *p_z, *p_di, *p_do;
    cudaGetSymbolAddress(&p_hh, g_hh);
    cudaGetSymbolAddress(&p_z, g_z);
    cudaGetSymbolAddress(&p_di, g_degin);
    cudaGetSymbolAddress(&p_do, g_degout);

    cudaMemsetAsync(p_di, 0, sizeof(int) * NN);
    cudaMemsetAsync(p_do, 0, sizeof(int) * NN);

    // degrees + norms + CSR (dst-bucketed) build
    count_k<<<(NE + 255) / 256, 256>>>(src, dst);
    norm_k<<<(NN + 255) / 256, 256>>>();
    blocksum_k<<<NB, 256>>>();
    scanbsum_k<<<1, 512>>>();
    rowptr_k<<<NB, 256>>>();
    fill_k<<<(NE + 255) / 256, 256>>>(src, dst);

    // Layer 1: h = fp16((x @ W1) * norm_src) ; z = relu(agg1 * norm_dst + b1)
    packW_k<<<(64 * FD + 255) / 256, 256>>>(W1);
    gemm_k<<<(NN + 63) / 64, 256>>>(x, (__half*)p_hh);
    gather1_k<<<(NN * 32 + 255) / 256, 256>>>(b1);

    // Layer 2: h = fp16((z @ W2) * norm_src) ; fused gather -> per-node a, c
    packW_k<<<(64 * FD + 255) / 256, 256>>>(W2);
    gemm_k<<<(NN + 63) / 64, 256>>>((const float*)p_z, (__half*)p_hh);
    gather2_k<<<(NN * 32 + 255) / 256, 256>>>(b2, Wp);

    // Per-edge score
    edgescore_k<<<(NE + 255) / 256, 256>>>(src, dst, bp, out);
}

// round 8
// speedup vs baseline: 2.9214x; 1.5361x over previous
#include <cuda_runtime.h>
#include <cuda_fp16.h>

#define NN 100000
#define NE 1600000
#define FD 128
#define NB 391            // ceil(NN / 256)
#define SA_STRIDE 136     // 128 + 8 halves pad -> conflict-free ldmatrix
#define SW_STRIDE 136

// ---- scratch (static device arrays; no runtime alloc allowed) ----
static __device__ __half g_hh[(size_t)NN * FD];   // post-GEMM node features (fp16)
static __device__ float  g_z[(size_t)NN * FD];    // relu(agg1*nd + b1) = GEMM2 input (fp32)
static __device__ __half g_Wh[FD * FD];           // current-layer W in fp16
static __device__ int    g_degout[NN];
static __device__ int    g_degin[NN];
static __device__ float  g_nsrc[NN];
static __device__ float  g_ndst[NN];
static __device__ int    g_rowptr[NN + 1];
static __device__ int    g_cursor[NN];
static __device__ int    g_csr[NE];               // src ids bucketed by dst
static __device__ int    g_bsum[512];
static __device__ float  g_a[NN];                 // dot(h2, Wp[:128])
static __device__ float  g_c[NN];                 // dot(h2, Wp[128:])

// ---- degree counting ----
__global__ void count_k(const int* __restrict__ src, const int* __restrict__ dst) {
    int e = blockIdx.x * blockDim.x + threadIdx.x;
    if (e < NE) {
        atomicAdd(&g_degout[src[e]], 1);
        atomicAdd(&g_degin[dst[e]], 1);
    }
}

__global__ void norm_k() {
    int i = blockIdx.x * blockDim.x + threadIdx.x;
    if (i < NN) {
        g_nsrc[i] = rsqrtf(fmaxf((float)g_degout[i], 1.0f));
        g_ndst[i] = rsqrtf(fmaxf((float)g_degin[i], 1.0f));
    }
}

// ---- W fp32 -> fp16 ----
__global__ void packW_k(const float* __restrict__ W) {
    int i = blockIdx.x * blockDim.x + threadIdx.x;
    if (i < FD * FD) g_Wh[i] = __float2half(__ldg(W + i));
}

// ---- CSR build ----
__global__ void blocksum_k() {
    int i = blockIdx.x * 256 + threadIdx.x;
    int v = (i < NN) ? g_degin[i] : 0;
#pragma unroll
    for (int off = 16; off > 0; off >>= 1) v += __shfl_xor_sync(0xffffffffu, v, off);
    __shared__ int s[8];
    int lane = threadIdx.x & 31, wid = threadIdx.x >> 5;
    if (lane == 0) s[wid] = v;
    __syncthreads();
    if (threadIdx.x == 0) {
        int t = 0;
#pragma unroll
        for (int w = 0; w < 8; w++) t += s[w];
        g_bsum[blockIdx.x] = t;
    }
}

__global__ void scanbsum_k() {   // single block, exclusive scan of NB block sums
    __shared__ int sh[512];
    int t = threadIdx.x;
    int v = (t < NB) ? g_bsum[t] : 0;
    sh[t] = v;
    __syncthreads();
    for (int off = 1; off < 512; off <<= 1) {
        int a = (t >= off) ? sh[t - off] : 0;
        __syncthreads();
        sh[t] += a;
        __syncthreads();
    }
    if (t < NB) g_bsum[t] = sh[t] - v;   // exclusive
}

__global__ void rowptr_k() {
    int i = blockIdx.x * 256 + threadIdx.x;
    int lane = threadIdx.x & 31, wid = threadIdx.x >> 5;
    int v = (i < NN) ? g_degin[i] : 0;
    int incl = v;
#pragma unroll
    for (int off = 1; off < 32; off <<= 1) {
        int n = __shfl_up_sync(0xffffffffu, incl, off);
        if (lane >= off) incl += n;
    }
    __shared__ int ws[8];
    if (lane == 31) ws[wid] = incl;
    __syncthreads();
    if (threadIdx.x == 0) {
        int run = 0;
#pragma unroll
        for (int w = 0; w < 8; w++) { int t = ws[w]; ws[w] = run; run += t; }
    }
    __syncthreads();
    int excl = incl - v + ws[wid] + g_bsum[blockIdx.x];
    if (i < NN) {
        g_rowptr[i] = excl;
        g_cursor[i] = excl;
        if (i == NN - 1) g_rowptr[NN] = excl + v;
    }
}

__global__ void fill_k(const int* __restrict__ src, const int* __restrict__ dst) {
    int e = blockIdx.x * blockDim.x + threadIdx.x;
    if (e < NE) {
        int d = dst[e];
        int pos = atomicAdd(&g_cursor[d], 1);
        g_csr[pos] = src[e];
    }
}

// ---- HMMA helpers ----
__device__ __forceinline__ unsigned smem_u32(const void* p) {
    return (unsigned)__cvta_generic_to_shared(p);
}

__device__ __forceinline__ void ldsm_x4(unsigned& r0, unsigned& r1, unsigned& r2,
                                        unsigned& r3, unsigned addr) {
    asm volatile("ldmatrix.sync.aligned.m8n8.x4.shared.b16 {%0,%1,%2,%3}, [%4];"
                 : "=r"(r0), "=r"(r1), "=r"(r2), "=r"(r3) : "r"(addr));
}

__device__ __forceinline__ void ldsm_x4_t(unsigned& r0, unsigned& r1, unsigned& r2,
                                          unsigned& r3, unsigned addr) {
    asm volatile("ldmatrix.sync.aligned.m8n8.x4.trans.shared.b16 {%0,%1,%2,%3}, [%4];"
                 : "=r"(r0), "=r"(r1), "=r"(r2), "=r"(r3) : "r"(addr));
}

__device__ __forceinline__ void mma16816(float4& c, unsigned a0, unsigned a1,
                                         unsigned a2, unsigned a3,
                                         unsigned b0, unsigned b1) {
    asm volatile("mma.sync.aligned.m16n8k16.row.col.f32.f16.f16.f32 "
                 "{%0,%1,%2,%3}, {%4,%5,%6,%7}, {%8,%9}, {%0,%1,%2,%3};"
                 : "+f"(c.x), "+f"(c.y), "+f"(c.z), "+f"(c.w)
                 : "r"(a0), "r"(a1), "r"(a2), "r"(a3), "r"(b0), "r"(b1));
}

// ---- GEMM: out[i][:] = fp16( norm_src[i] * (in[i][:] @ W) ), tensor cores ----
// Block: 256 thr / 8 warps, 32 rows x 128 cols. Full W tile staged in smem.
// Warp w: m-tile = w&1 (16 rows), n-quarter = w>>1 (32 cols = 4 n-tiles of 8).
__global__ __launch_bounds__(256) void gemm_k(const float* __restrict__ in,
                                              __half* __restrict__ out) {
    __shared__ __half sA[32 * SA_STRIDE];
    __shared__ __half sW[FD * SW_STRIDE];
    const int tid = threadIdx.x;
    const int row0 = blockIdx.x * 32;

    // stage W (fp16, already packed): 128 rows x 128 cols, 8 halves per copy
    for (int i = tid; i < FD * 16; i += 256) {
        int r = i >> 4;
        int c8 = (i & 15) << 3;
        uint4 v = *reinterpret_cast<const uint4*>(g_Wh + r * FD + c8);
        *reinterpret_cast<uint4*>(&sW[r * SW_STRIDE + c8]) = v;
    }
    // stage 32 input rows, fp32 -> fp16
    for (int i = tid; i < 32 * 16; i += 256) {
        int r = i >> 4;
        int c8 = (i & 15) << 3;
        int gr = row0 + r;
        uint4 st = make_uint4(0u, 0u, 0u, 0u);
        if (gr < NN) {
            float4 f0 = *reinterpret_cast<const float4*>(in + (size_t)gr * FD + c8);
            float4 f1 = *reinterpret_cast<const float4*>(in + (size_t)gr * FD + c8 + 4);
            __half2 h0 = __floats2half2_rn(f0.x, f0.y);
            __half2 h1 = __floats2half2_rn(f0.z, f0.w);
            __half2 h2 = __floats2half2_rn(f1.x, f1.y);
            __half2 h3 = __floats2half2_rn(f1.z, f1.w);
            st.x = *reinterpret_cast<unsigned*>(&h0);
            st.y = *reinterpret_cast<unsigned*>(&h1);
            st.z = *reinterpret_cast<unsigned*>(&h2);
            st.w = *reinterpret_cast<unsigned*>(&h3);
        }
        *reinterpret_cast<uint4*>(&sA[r * SA_STRIDE + c8]) = st;
    }
    __syncthreads();

    const int lane = tid & 31;
    const int wid = tid >> 5;
    const int m0 = (wid & 1) << 4;      // 0 or 16
    const int n0 = (wid >> 1) << 5;     // 0,32,64,96

    float4 c[4];
#pragma unroll
    for (int j = 0; j < 4; j++) c[j] = make_float4(0.f, 0.f, 0.f, 0.f);

    const int lm = lane >> 3;           // ldmatrix matrix id
    const int lr = lane & 7;            // row within matrix
    const int arow = m0 + ((lm & 1) << 3) + lr;
    const int koff = (lm >> 1) << 3;

#pragma unroll
    for (int ks = 0; ks < 8; ks++) {
        int k0 = ks << 4;
        unsigned a0, a1, a2, a3;
        ldsm_x4(a0, a1, a2, a3, smem_u32(&sA[arow * SA_STRIDE + k0 + koff]));
#pragma unroll
        for (int j = 0; j < 2; j++) {
            int n = n0 + (j << 4);
            unsigned b0, b1, b2, b3;
            // rows = k, cols = n : .trans yields col-major B fragments
            ldsm_x4_t(b0, b1, b2, b3,
                      smem_u32(&sW[(k0 + ((lm & 1) << 3) + lr) * SW_STRIDE + n + koff]));
            mma16816(c[2 * j],     a0, a1, a2, a3, b0, b1);
            mma16816(c[2 * j + 1], a0, a1, a2, a3, b2, b3);
        }
    }

    // epilogue: scale by norm_src, convert fp16, store
    const int rA = row0 + m0 + (lane >> 2);
    const int rB = rA + 8;
    float nsA = (rA < NN) ? g_nsrc[rA] : 0.f;
    float nsB = (rB < NN) ? g_nsrc[rB] : 0.f;
#pragma unroll
    for (int j = 0; j < 4; j++) {
        int col = n0 + (j << 3) + ((lane & 3) << 1);
        if (rA < NN) {
            __half2 h = __floats2half2_rn(c[j].x * nsA, c[j].y * nsA);
            *reinterpret_cast<__half2*>(out + (size_t)rA * FD + col) = h;
        }
        if (rB < NN) {
            __half2 h = __floats2half2_rn(c[j].z * nsB, c[j].w * nsB);
            *reinterpret_cast<__half2*>(out + (size_t)rB * FD + col) = h;
        }
    }
}

// ---- warp-per-node CSR accumulate over fp16 rows (fp32 accum), unroll-4 ----
__device__ __forceinline__ float4 csr_accum(int node, int lane) {
    int beg = g_rowptr[node];
    int end = g_rowptr[node + 1];
    float4 acc = make_float4(0.f, 0.f, 0.f, 0.f);
    int j = beg;
    for (; j + 4 <= end; j += 4) {
        int s0 = __ldg(g_csr + j);
        int s1 = __ldg(g_csr + j + 1);
        int s2 = __ldg(g_csr + j + 2);
        int s3 = __ldg(g_csr + j + 3);
        uint2 u0 = *reinterpret_cast<const uint2*>(g_hh + (size_t)s0 * FD + lane * 4);
        uint2 u1 = *reinterpret_cast<const uint2*>(g_hh + (size_t)s1 * FD + lane * 4);
        uint2 u2 = *reinterpret_cast<const uint2*>(g_hh + (size_t)s2 * FD + lane * 4);
        uint2 u3 = *reinterpret_cast<const uint2*>(g_hh + (size_t)s3 * FD + lane * 4);
        float2 a0 = __half22float2(*reinterpret_cast<__half2*>(&u0.x));
        float2 b0 = __half22float2(*reinterpret_cast<__half2*>(&u0.y));
        float2 a1 = __half22float2(*reinterpret_cast<__half2*>(&u1.x));
        float2 b1 = __half22float2(*reinterpret_cast<__half2*>(&u1.y));
        float2 a2 = __half22float2(*reinterpret_cast<__half2*>(&u2.x));
        float2 b2 = __half22float2(*reinterpret_cast<__half2*>(&u2.y));
        float2 a3 = __half22float2(*reinterpret_cast<__half2*>(&u3.x));
        float2 b3 = __half22float2(*reinterpret_cast<__half2*>(&u3.y));
        acc.x += (a0.x + a1.x) + (a2.x + a3.x);
        acc.y += (a0.y + a1.y) + (a2.y + a3.y);
        acc.z += (b0.x + b1.x) + (b2.x + b3.x);
        acc.w += (b0.y + b1.y) + (b2.y + b3.y);
    }
    for (; j < end; j++) {
        int s = __ldg(g_csr + j);
        uint2 u = *reinterpret_cast<const uint2*>(g_hh + (size_t)s * FD + lane * 4);
        float2 a = __half22float2(*reinterpret_cast<__half2*>(&u.x));
        float2 b = __half22float2(*reinterpret_cast<__half2*>(&u.y));
        acc.x += a.x; acc.y += a.y; acc.z += b.x; acc.w += b.y;
    }
    return acc;
}

// ---- layer 1 aggregate, fused epilogue: z = relu(agg*nd + b1) (fp32) ----
__global__ __launch_bounds__(256) void gather1_k(const float* __restrict__ b1) {
    int w = (blockIdx.x * 256 + threadIdx.x) >> 5;
    if (w >= NN) return;
    int lane = threadIdx.x & 31;
    float4 acc = csr_accum(w, lane);
    float nd = g_ndst[w];
    float4 b = __ldg(reinterpret_cast<const float4*>(b1 + lane * 4));
    float4 o;
    o.x = fmaxf(fmaf(acc.x, nd, b.x), 0.f);
    o.y = fmaxf(fmaf(acc.y, nd, b.y), 0.f);
    o.z = fmaxf(fmaf(acc.z, nd, b.z), 0.f);
    o.w = fmaxf(fmaf(acc.w, nd, b.w), 0.f);
    *reinterpret_cast<float4*>(g_z + (size_t)w * FD + lane * 4) = o;
}

// ---- layer 2 aggregate, fused link-predictor projection: a[i], c[i] ----
__global__ __launch_bounds__(256) void gather2_k(const float* __restrict__ b2,
                                                 const float* __restrict__ Wp) {
    int w = (blockIdx.x * 256 + threadIdx.x) >> 5;
    if (w >= NN) return;
    int lane = threadIdx.x & 31;
    float4 acc = csr_accum(w, lane);
    float nd = g_ndst[w];
    float4 b  = __ldg(reinterpret_cast<const float4*>(b2 + lane * 4));
    float4 w1 = __ldg(reinterpret_cast<const float4*>(Wp + lane * 4));
    float4 w2 = __ldg(reinterpret_cast<const float4*>(Wp + FD + lane * 4));
    float hx = fmaf(acc.x, nd, b.x);
    float hy = fmaf(acc.y, nd, b.y);
    float hz = fmaf(acc.z, nd, b.z);
    float hw = fmaf(acc.w, nd, b.w);
    float av = hx * w1.x + hy * w1.y + hz * w1.z + hw * w1.w;
    float cv = hx * w2.x + hy * w2.y + hz * w2.z + hw * w2.w;
#pragma unroll
    for (int off = 16; off > 0; off >>= 1) {
        av += __shfl_xor_sync(0xffffffffu, av, off);
        cv += __shfl_xor_sync(0xffffffffu, cv, off);
    }
    if (lane == 0) { g_a[w] = av; g_c[w] = cv; }
}

// ---- final per-edge score: sigmoid(a[src] + c[dst] + bp) ----
__global__ void edgescore_k(const int* __restrict__ src, const int* __restrict__ dst,
                            const float* __restrict__ bp, float* __restrict__ out) {
    int e = blockIdx.x * blockDim.x + threadIdx.x;
    if (e < NE) {
        float z = g_a[__ldg(src + e)] + g_c[__ldg(dst + e)] + __ldg(bp);
        out[e] = 1.0f / (1.0f + expf(-z));
    }
}

extern "C" void kernel_launch(void* const* d_in, const int* in_sizes, int n_in,
                              void* d_out, int out_size) {
    (void)in_sizes; (void)n_in; (void)out_size;
    const float* x  = (const float*)d_in[0];
    const float* W1 = (const float*)d_in[1];
    const float* b1 = (const float*)d_in[2];
    const float* W2 = (const float*)d_in[3];
    const float* b2 = (const float*)d_in[4];
    const float* Wp = (const float*)d_in[5];
    const float* bp = (const float*)d_in[6];
    const int* src  = (const int*)d_in[7];
    const int* dst  = (const int*)d_in[8];
    float* out = (float*)d_out;

    void *p_hh, *p_z, *p_di, *p_do;
    cudaGetSymbolAddress(&p_hh, g_hh);
    cudaGetSymbolAddress(&p_z, g_z);
    cudaGetSymbolAddress(&p_di, g_degin);
    cudaGetSymbolAddress(&p_do, g_degout);

    cudaMemsetAsync(p_di, 0, sizeof(int) * NN);
    cudaMemsetAsync(p_do, 0, sizeof(int) * NN);

    // degrees + norms, then GEMM1 EARLY so ncu (-s 5 -c 1) profiles gemm_k
    count_k<<<(NE + 255) / 256, 256>>>(src, dst);
    norm_k<<<(NN + 255) / 256, 256>>>();
    packW_k<<<(FD * FD + 255) / 256, 256>>>(W1);
    gemm_k<<<(NN + 31) / 32, 256>>>(x, (__half*)p_hh);          // <- profiled launch

    // CSR (dst-bucketed) build
    blocksum_k<<<NB, 256>>>();
    scanbsum_k<<<1, 512>>>();
    rowptr_k<<<NB, 256>>>();
    fill_k<<<(NE + 255) / 256, 256>>>(src, dst);

    // Layer 1 aggregate: z = relu(agg1 * norm_dst + b1)
    gather1_k<<<(NN * 32 + 255) / 256, 256>>>(b1);

    // Layer 2: h = fp16((z @ W2) * norm_src) ; fused gather -> per-node a, c
    packW_k<<<(FD * FD + 255) / 256, 256>>>(W2);
    gemm_k<<<(NN + 31) / 32, 256>>>((const float*)p_z, (__half*)p_hh);
    gather2_k<<<(NN * 32 + 255) / 256, 256>>>(b2, Wp);

    // Per-edge score
    edgescore_k<<<(NE + 255) / 256, 256>>>(src, dst, bp, out);
}

// round 9
// speedup vs baseline: 2.9346x; 1.0045x over previous
#include <cuda_runtime.h>
#include <cuda_fp16.h>

#define NN 100000
#define NE 1600000
#define FD 128
#define NB 391            // ceil(NN / 256)
#define SA_STRIDE 136     // 128 + 8 halves pad -> conflict-free ldmatrix
#define SW_STRIDE 136
#define ROWS_PER_BLK 128  // 4 chunks of 32 rows; W staged once per block

// ---- scratch (static device arrays; no runtime alloc allowed) ----
static __device__ __half g_hh[(size_t)NN * FD];   // post-GEMM node features (fp16)
static __device__ float  g_z[(size_t)NN * FD];    // relu(agg1*nd + b1) = GEMM2 input (fp32)
static __device__ __half g_Wh[FD * FD];           // current-layer W in fp16
static __device__ int    g_degout[NN];
static __device__ int    g_degin[NN];
static __device__ float  g_nsrc[NN];
static __device__ float  g_ndst[NN];
static __device__ int    g_rowptr[NN + 1];
static __device__ int    g_cursor[NN];
static __device__ int    g_csr[NE];               // src ids bucketed by dst
static __device__ int    g_bsum[512];
static __device__ float  g_a[NN];                 // dot(h2, Wp[:128])
static __device__ float  g_c[NN];                 // dot(h2, Wp[128:])

// ---- degree counting ----
__global__ void count_k(const int* __restrict__ src, const int* __restrict__ dst) {
    int e = blockIdx.x * blockDim.x + threadIdx.x;
    if (e < NE) {
        atomicAdd(&g_degout[src[e]], 1);
        atomicAdd(&g_degin[dst[e]], 1);
    }
}

__global__ void norm_k() {
    int i = blockIdx.x * blockDim.x + threadIdx.x;
    if (i < NN) {
        g_nsrc[i] = rsqrtf(fmaxf((float)g_degout[i], 1.0f));
        g_ndst[i] = rsqrtf(fmaxf((float)g_degin[i], 1.0f));
    }
}

// ---- W fp32 -> fp16 ----
__global__ void packW_k(const float* __restrict__ W) {
    int i = blockIdx.x * blockDim.x + threadIdx.x;
    if (i < FD * FD) g_Wh[i] = __float2half(__ldg(W + i));
}

// ---- CSR build ----
__global__ void blocksum_k() {
    int i = blockIdx.x * 256 + threadIdx.x;
    int v = (i < NN) ? g_degin[i] : 0;
#pragma unroll
    for (int off = 16; off > 0; off >>= 1) v += __shfl_xor_sync(0xffffffffu, v, off);
    __shared__ int s[8];
    int lane = threadIdx.x & 31, wid = threadIdx.x >> 5;
    if (lane == 0) s[wid] = v;
    __syncthreads();
    if (threadIdx.x == 0) {
        int t = 0;
#pragma unroll
        for (int w = 0; w < 8; w++) t += s[w];
        g_bsum[blockIdx.x] = t;
    }
}

__global__ void scanbsum_k() {   // single block, exclusive scan of NB block sums
    __shared__ int sh[512];
    int t = threadIdx.x;
    int v = (t < NB) ? g_bsum[t] : 0;
    sh[t] = v;
    __syncthreads();
    for (int off = 1; off < 512; off <<= 1) {
        int a = (t >= off) ? sh[t - off] : 0;
        __syncthreads();
        sh[t] += a;
        __syncthreads();
    }
    if (t < NB) g_bsum[t] = sh[t] - v;   // exclusive
}

__global__ void rowptr_k() {
    int i = blockIdx.x * 256 + threadIdx.x;
    int lane = threadIdx.x & 31, wid = threadIdx.x >> 5;
    int v = (i < NN) ? g_degin[i] : 0;
    int incl = v;
#pragma unroll
    for (int off = 1; off < 32; off <<= 1) {
        int n = __shfl_up_sync(0xffffffffu, incl, off);
        if (lane >= off) incl += n;
    }
    __shared__ int ws[8];
    if (lane == 31) ws[wid] = incl;
    __syncthreads();
    if (threadIdx.x == 0) {
        int run = 0;
#pragma unroll
        for (int w = 0; w < 8; w++) { int t = ws[w]; ws[w] = run; run += t; }
    }
    __syncthreads();
    int excl = incl - v + ws[wid] + g_bsum[blockIdx.x];
    if (i < NN) {
        g_rowptr[i] = excl;
        g_cursor[i] = excl;
        if (i == NN - 1) g_rowptr[NN] = excl + v;
    }
}

__global__ void fill_k(const int* __restrict__ src, const int* __restrict__ dst) {
    int e = blockIdx.x * blockDim.x + threadIdx.x;
    if (e < NE) {
        int d = dst[e];
        int pos = atomicAdd(&g_cursor[d], 1);
        g_csr[pos] = src[e];
    }
}

// ---- HMMA helpers ----
__device__ __forceinline__ unsigned smem_u32(const void* p) {
    return (unsigned)__cvta_generic_to_shared(p);
}

__device__ __forceinline__ void ldsm_x4(unsigned& r0, unsigned& r1, unsigned& r2,
                                        unsigned& r3, unsigned addr) {
    asm volatile("ldmatrix.sync.aligned.m8n8.x4.shared.b16 {%0,%1,%2,%3}, [%4];"
                 : "=r"(r0), "=r"(r1), "=r"(r2), "=r"(r3) : "r"(addr));
}

__device__ __forceinline__ void ldsm_x4_t(unsigned& r0, unsigned& r1, unsigned& r2,
                                          unsigned& r3, unsigned addr) {
    asm volatile("ldmatrix.sync.aligned.m8n8.x4.trans.shared.b16 {%0,%1,%2,%3}, [%4];"
                 : "=r"(r0), "=r"(r1), "=r"(r2), "=r"(r3) : "r"(addr));
}

__device__ __forceinline__ void mma16816(float4& c, unsigned a0, unsigned a1,
                                         unsigned a2, unsigned a3,
                                         unsigned b0, unsigned b1) {
    asm volatile("mma.sync.aligned.m16n8k16.row.col.f32.f16.f16.f32 "
                 "{%0,%1,%2,%3}, {%4,%5,%6,%7}, {%8,%9}, {%0,%1,%2,%3};"
                 : "+f"(c.x), "+f"(c.y), "+f"(c.z), "+f"(c.w)
                 : "r"(a0), "r"(a1), "r"(a2), "r"(a3), "r"(b0), "r"(b1));
}

// ---- GEMM: out[i][:] = fp16( norm_src[i] * (in[i][:] @ W) ), tensor cores ----
// Block: 256 thr / 8 warps, 128 rows per block in 4 chunks of 32; full W tile
// staged in smem ONCE and reused across chunks (4x less W staging traffic).
// Per chunk, warp w: m-tile = w&1 (16 rows), n-quarter = w>>1 (32 cols).
__global__ __launch_bounds__(256) void gemm_k(const float* __restrict__ in,
                                              __half* __restrict__ out) {
    __shared__ __half sA[32 * SA_STRIDE];
    __shared__ __half sW[FD * SW_STRIDE];
    const int tid = threadIdx.x;
    const int blk0 = blockIdx.x * ROWS_PER_BLK;

    // stage W (fp16, already packed): 128 rows x 128 cols, 8 halves per copy
    for (int i = tid; i < FD * 16; i += 256) {
        int r = i >> 4;
        int c8 = (i & 15) << 3;
        uint4 v = *reinterpret_cast<const uint4*>(g_Wh + r * FD + c8);
        *reinterpret_cast<uint4*>(&sW[r * SW_STRIDE + c8]) = v;
    }

    const int lane = tid & 31;
    const int wid = tid >> 5;
    const int m0 = (wid & 1) << 4;      // 0 or 16
    const int n0 = (wid >> 1) << 5;     // 0,32,64,96
    const int lm = lane >> 3;           // ldmatrix matrix id
    const int lr = lane & 7;            // row within matrix
    const int arow = m0 + ((lm & 1) << 3) + lr;
    const int koff = (lm >> 1) << 3;

#pragma unroll
    for (int chunk = 0; chunk < 4; chunk++) {
        const int row0 = blk0 + chunk * 32;
        __syncthreads();   // protect sA from previous chunk's readers

        // stage 32 input rows, fp32 -> fp16
        for (int i = tid; i < 32 * 16; i += 256) {
            int r = i >> 4;
            int c8 = (i & 15) << 3;
            int gr = row0 + r;
            uint4 st = make_uint4(0u, 0u, 0u, 0u);
            if (gr < NN) {
                float4 f0 = *reinterpret_cast<const float4*>(in + (size_t)gr * FD + c8);
                float4 f1 = *reinterpret_cast<const float4*>(in + (size_t)gr * FD + c8 + 4);
                __half2 h0 = __floats2half2_rn(f0.x, f0.y);
                __half2 h1 = __floats2half2_rn(f0.z, f0.w);
                __half2 h2 = __floats2half2_rn(f1.x, f1.y);
                __half2 h3 = __floats2half2_rn(f1.z, f1.w);
                st.x = *reinterpret_cast<unsigned*>(&h0);
                st.y = *reinterpret_cast<unsigned*>(&h1);
                st.z = *reinterpret_cast<unsigned*>(&h2);
                st.w = *reinterpret_cast<unsigned*>(&h3);
            }
            *reinterpret_cast<uint4*>(&sA[r * SA_STRIDE + c8]) = st;
        }
        __syncthreads();

        float4 c[4];
#pragma unroll
        for (int j = 0; j < 4; j++) c[j] = make_float4(0.f, 0.f, 0.f, 0.f);

#pragma unroll
        for (int ks = 0; ks < 8; ks++) {
            int k0 = ks << 4;
            unsigned a0, a1, a2, a3;
            ldsm_x4(a0, a1, a2, a3, smem_u32(&sA[arow * SA_STRIDE + k0 + koff]));
#pragma unroll
            for (int j = 0; j < 2; j++) {
                int n = n0 + (j << 4);
                unsigned b0, b1, b2, b3;
                // rows = k, cols = n : .trans yields col-major B fragments
                ldsm_x4_t(b0, b1, b2, b3,
                          smem_u32(&sW[(k0 + ((lm & 1) << 3) + lr) * SW_STRIDE + n + koff]));
                mma16816(c[2 * j],     a0, a1, a2, a3, b0, b1);
                mma16816(c[2 * j + 1], a0, a1, a2, a3, b2, b3);
            }
        }

        // epilogue: scale by norm_src, convert fp16, store
        const int rA = row0 + m0 + (lane >> 2);
        const int rB = rA + 8;
        float nsA = (rA < NN) ? g_nsrc[rA] : 0.f;
        float nsB = (rB < NN) ? g_nsrc[rB] : 0.f;
#pragma unroll
        for (int j = 0; j < 4; j++) {
            int col = n0 + (j << 3) + ((lane & 3) << 1);
            if (rA < NN) {
                __half2 h = __floats2half2_rn(c[j].x * nsA, c[j].y * nsA);
                *reinterpret_cast<__half2*>(out + (size_t)rA * FD + col) = h;
            }
            if (rB < NN) {
                __half2 h = __floats2half2_rn(c[j].z * nsB, c[j].w * nsB);
                *reinterpret_cast<__half2*>(out + (size_t)rB * FD + col) = h;
            }
        }
    }
}

// ---- warp-per-node CSR accumulate over fp16 rows (fp32 accum), unroll-4 ----
__device__ __forceinline__ float4 csr_accum(int node, int lane) {
    int beg = g_rowptr[node];
    int end = g_rowptr[node + 1];
    float4 acc = make_float4(0.f, 0.f, 0.f, 0.f);
    int j = beg;
    for (; j + 4 <= end; j += 4) {
        int s0 = __ldg(g_csr + j);
        int s1 = __ldg(g_csr + j + 1);
        int s2 = __ldg(g_csr + j + 2);
        int s3 = __ldg(g_csr + j + 3);
        uint2 u0 = *reinterpret_cast<const uint2*>(g_hh + (size_t)s0 * FD + lane * 4);
        uint2 u1 = *reinterpret_cast<const uint2*>(g_hh + (size_t)s1 * FD + lane * 4);
        uint2 u2 = *reinterpret_cast<const uint2*>(g_hh + (size_t)s2 * FD + lane * 4);
        uint2 u3 = *reinterpret_cast<const uint2*>(g_hh + (size_t)s3 * FD + lane * 4);
        float2 a0 = __half22float2(*reinterpret_cast<__half2*>(&u0.x));
        float2 b0 = __half22float2(*reinterpret_cast<__half2*>(&u0.y));
        float2 a1 = __half22float2(*reinterpret_cast<__half2*>(&u1.x));
        float2 b1 = __half22float2(*reinterpret_cast<__half2*>(&u1.y));
        float2 a2 = __half22float2(*reinterpret_cast<__half2*>(&u2.x));
        float2 b2 = __half22float2(*reinterpret_cast<__half2*>(&u2.y));
        float2 a3 = __half22float2(*reinterpret_cast<__half2*>(&u3.x));
        float2 b3 = __half22float2(*reinterpret_cast<__half2*>(&u3.y));
        acc.x += (a0.x + a1.x) + (a2.x + a3.x);
        acc.y += (a0.y + a1.y) + (a2.y + a3.y);
        acc.z += (b0.x + b1.x) + (b2.x + b3.x);
        acc.w += (b0.y + b1.y) + (b2.y + b3.y);
    }
    for (; j < end; j++) {
        int s = __ldg(g_csr + j);
        uint2 u = *reinterpret_cast<const uint2*>(g_hh + (size_t)s * FD + lane * 4);
        float2 a = __half22float2(*reinterpret_cast<__half2*>(&u.x));
        float2 b = __half22float2(*reinterpret_cast<__half2*>(&u.y));
        acc.x += a.x; acc.y += a.y; acc.z += b.x; acc.w += b.y;
    }
    return acc;
}

// ---- layer 1 aggregate, fused epilogue: z = relu(agg*nd + b1) (fp32) ----
__global__ __launch_bounds__(256) void gather1_k(const float* __restrict__ b1) {
    int w = (blockIdx.x * 256 + threadIdx.x) >> 5;
    if (w >= NN) return;
    int lane = threadIdx.x & 31;
    float4 acc = csr_accum(w, lane);
    float nd = g_ndst[w];
    float4 b = __ldg(reinterpret_cast<const float4*>(b1 + lane * 4));
    float4 o;
    o.x = fmaxf(fmaf(acc.x, nd, b.x), 0.f);
    o.y = fmaxf(fmaf(acc.y, nd, b.y), 0.f);
    o.z = fmaxf(fmaf(acc.z, nd, b.z), 0.f);
    o.w = fmaxf(fmaf(acc.w, nd, b.w), 0.f);
    *reinterpret_cast<float4*>(g_z + (size_t)w * FD + lane * 4) = o;
}

// ---- layer 2 aggregate, fused link-predictor projection: a[i], c[i] ----
__global__ __launch_bounds__(256) void gather2_k(const float* __restrict__ b2,
                                                 const float* __restrict__ Wp) {
    int w = (blockIdx.x * 256 + threadIdx.x) >> 5;
    if (w >= NN) return;
    int lane = threadIdx.x & 31;
    float4 acc = csr_accum(w, lane);
    float nd = g_ndst[w];
    float4 b  = __ldg(reinterpret_cast<const float4*>(b2 + lane * 4));
    float4 w1 = __ldg(reinterpret_cast<const float4*>(Wp + lane * 4));
    float4 w2 = __ldg(reinterpret_cast<const float4*>(Wp + FD + lane * 4));
    float hx = fmaf(acc.x, nd, b.x);
    float hy = fmaf(acc.y, nd, b.y);
    float hz = fmaf(acc.z, nd, b.z);
    float hw = fmaf(acc.w, nd, b.w);
    float av = hx * w1.x + hy * w1.y + hz * w1.z + hw * w1.w;
    float cv = hx * w2.x + hy * w2.y + hz * w2.z + hw * w2.w;
#pragma unroll
    for (int off = 16; off > 0; off >>= 1) {
        av += __shfl_xor_sync(0xffffffffu, av, off);
        cv += __shfl_xor_sync(0xffffffffu, cv, off);
    }
    if (lane == 0) { g_a[w] = av; g_c[w] = cv; }
}

// ---- final per-edge score: sigmoid(a[src] + c[dst] + bp) ----
__global__ void edgescore_k(const int* __restrict__ src, const int* __restrict__ dst,
                            const float* __restrict__ bp, float* __restrict__ out) {
    int e = blockIdx.x * blockDim.x + threadIdx.x;
    if (e < NE) {
        float z = g_a[__ldg(src + e)] + g_c[__ldg(dst + e)] + __ldg(bp);
        out[e] = 1.0f / (1.0f + expf(-z));
    }
}

extern "C" void kernel_launch(void* const* d_in, const int* in_sizes, int n_in,
                              void* d_out, int out_size) {
    (void)in_sizes; (void)n_in; (void)out_size;
    const float* x  = (const float*)d_in[0];
    const float* W1 = (const float*)d_in[1];
    const float* b1 = (const float*)d_in[2];
    const float* W2 = (const float*)d_in[3];
    const float* b2 = (const float*)d_in[4];
    const float* Wp = (const float*)d_in[5];
    const float* bp = (const float*)d_in[6];
    const int* src  = (const int*)d_in[7];
    const int* dst  = (const int*)d_in[8];
    float* out = (float*)d_out;

    void *p_hh, *p_z, *p_di, *p_do;
    cudaGetSymbolAddress(&p_hh, g_hh);
    cudaGetSymbolAddress(&p_z, g_z);
    cudaGetSymbolAddress(&p_di, g_degin);
    cudaGetSymbolAddress(&p_do, g_degout);

    cudaMemsetAsync(p_di, 0, sizeof(int) * NN);
    cudaMemsetAsync(p_do, 0, sizeof(int) * NN);

    // degrees + norms, then GEMM1 EARLY so ncu (-s 5 -c 1) profiles gemm_k
    count_k<<<(NE + 255) / 256, 256>>>(src, dst);
    norm_k<<<(NN + 255) / 256, 256>>>();
    packW_k<<<(FD * FD + 255) / 256, 256>>>(W1);
    gemm_k<<<(NN + ROWS_PER_BLK - 1) / ROWS_PER_BLK, 256>>>(x, (__half*)p_hh);  // profiled

    // CSR (dst-bucketed) build
    blocksum_k<<<NB, 256>>>();
    scanbsum_k<<<1, 512>>>();
    rowptr_k<<<NB, 256>>>();
    fill_k<<<(NE + 255) / 256, 256>>>(src, dst);

    // Layer 1 aggregate: z = relu(agg1 * norm_dst + b1)
    gather1_k<<<(NN * 32 + 255) / 256, 256>>>(b1);

    // Layer 2: h = fp16((z @ W2) * norm_src) ; fused gather -> per-node a, c
    packW_k<<<(FD * FD + 255) / 256, 256>>>(W2);
    gemm_k<<<(NN + ROWS_PER_BLK - 1) / ROWS_PER_BLK, 256>>>((const float*)p_z, (__half*)p_hh);
    gather2_k<<<(NN * 32 + 255) / 256, 256>>>(b2, Wp);

    // Per-edge score
    edgescore_k<<<(NE + 255) / 256, 256>>>(src, dst, bp, out);
}

// round 10
// speedup vs baseline: 3.1491x; 1.0731x over previous
#include <cuda_runtime.h>
#include <cuda_fp16.h>

#define NN 100000
#define NE 1600000
#define FD 128
#define NB 391            // ceil(NN / 256)
#define SA_STRIDE 136     // 128 + 8 halves pad -> conflict-free ldmatrix
#define SW_STRIDE 136
#define ROWS_PER_BLK 128  // 4 chunks of 32 rows; W staged once per block

// ---- scratch (static device arrays; no runtime alloc allowed) ----
static __device__ __half g_hh[(size_t)NN * FD];   // post-GEMM node features (fp16)
static __device__ __half g_zh[(size_t)NN * FD];   // relu(agg1*nd + b1) in fp16 (GEMM2 input)
static __device__ __half g_Wh[FD * FD];           // current-layer W in fp16
static __device__ int    g_degout[NN];
static __device__ int    g_degin[NN];
static __device__ float  g_nsrc[NN];
static __device__ float  g_ndst[NN];
static __device__ int    g_rowptr[NN + 1];
static __device__ int    g_cursor[NN];
static __device__ int    g_csr[NE];               // src ids bucketed by dst
static __device__ int    g_bsum[512];
static __device__ float  g_a[NN];                 // dot(h2, Wp[:128])
static __device__ float  g_c[NN];                 // dot(h2, Wp[128:])

// ---- degree counting ----
__global__ void count_k(const int* __restrict__ src, const int* __restrict__ dst) {
    int e = blockIdx.x * blockDim.x + threadIdx.x;
    if (e < NE) {
        atomicAdd(&g_degout[src[e]], 1);
        atomicAdd(&g_degin[dst[e]], 1);
    }
}

__global__ void norm_k() {
    int i = blockIdx.x * blockDim.x + threadIdx.x;
    if (i < NN) {
        g_nsrc[i] = rsqrtf(fmaxf((float)g_degout[i], 1.0f));
        g_ndst[i] = rsqrtf(fmaxf((float)g_degin[i], 1.0f));
    }
}

// ---- W fp32 -> fp16 ----
__global__ void packW_k(const float* __restrict__ W) {
    int i = blockIdx.x * blockDim.x + threadIdx.x;
    if (i < FD * FD) g_Wh[i] = __float2half(__ldg(W + i));
}

// ---- CSR build ----
__global__ void blocksum_k() {
    int i = blockIdx.x * 256 + threadIdx.x;
    int v = (i < NN) ? g_degin[i] : 0;
#pragma unroll
    for (int off = 16; off > 0; off >>= 1) v += __shfl_xor_sync(0xffffffffu, v, off);
    __shared__ int s[8];
    int lane = threadIdx.x & 31, wid = threadIdx.x >> 5;
    if (lane == 0) s[wid] = v;
    __syncthreads();
    if (threadIdx.x == 0) {
        int t = 0;
#pragma unroll
        for (int w = 0; w < 8; w++) t += s[w];
        g_bsum[blockIdx.x] = t;
    }
}

__global__ void scanbsum_k() {   // single block, exclusive scan of NB block sums
    __shared__ int sh[512];
    int t = threadIdx.x;
    int v = (t < NB) ? g_bsum[t] : 0;
    sh[t] = v;
    __syncthreads();
    for (int off = 1; off < 512; off <<= 1) {
        int a = (t >= off) ? sh[t - off] : 0;
        __syncthreads();
        sh[t] += a;
        __syncthreads();
    }
    if (t < NB) g_bsum[t] = sh[t] - v;   // exclusive
}

__global__ void rowptr_k() {
    int i = blockIdx.x * 256 + threadIdx.x;
    int lane = threadIdx.x & 31, wid = threadIdx.x >> 5;
    int v = (i < NN) ? g_degin[i] : 0;
    int incl = v;
#pragma unroll
    for (int off = 1; off < 32; off <<= 1) {
        int n = __shfl_up_sync(0xffffffffu, incl, off);
        if (lane >= off) incl += n;
    }
    __shared__ int ws[8];
    if (lane == 31) ws[wid] = incl;
    __syncthreads();
    if (threadIdx.x == 0) {
        int run = 0;
#pragma unroll
        for (int w = 0; w < 8; w++) { int t = ws[w]; ws[w] = run; run += t; }
    }
    __syncthreads();
    int excl = incl - v + ws[wid] + g_bsum[blockIdx.x];
    if (i < NN) {
        g_rowptr[i] = excl;
        g_cursor[i] = excl;
        if (i == NN - 1) g_rowptr[NN] = excl + v;
    }
}

__global__ void fill_k(const int* __restrict__ src, const int* __restrict__ dst) {
    int e = blockIdx.x * blockDim.x + threadIdx.x;
    if (e < NE) {
        int d = dst[e];
        int pos = atomicAdd(&g_cursor[d], 1);
        g_csr[pos] = src[e];
    }
}

// ---- HMMA helpers ----
__device__ __forceinline__ unsigned smem_u32(const void* p) {
    return (unsigned)__cvta_generic_to_shared(p);
}

__device__ __forceinline__ void ldsm_x4(unsigned& r0, unsigned& r1, unsigned& r2,
                                        unsigned& r3, unsigned addr) {
    asm volatile("ldmatrix.sync.aligned.m8n8.x4.shared.b16 {%0,%1,%2,%3}, [%4];"
                 : "=r"(r0), "=r"(r1), "=r"(r2), "=r"(r3) : "r"(addr));
}

__device__ __forceinline__ void ldsm_x4_t(unsigned& r0, unsigned& r1, unsigned& r2,
                                          unsigned& r3, unsigned addr) {
    asm volatile("ldmatrix.sync.aligned.m8n8.x4.trans.shared.b16 {%0,%1,%2,%3}, [%4];"
                 : "=r"(r0), "=r"(r1), "=r"(r2), "=r"(r3) : "r"(addr));
}

__device__ __forceinline__ void mma16816(float4& c, unsigned a0, unsigned a1,
                                         unsigned a2, unsigned a3,
                                         unsigned b0, unsigned b1) {
    asm volatile("mma.sync.aligned.m16n8k16.row.col.f32.f16.f16.f32 "
                 "{%0,%1,%2,%3}, {%4,%5,%6,%7}, {%8,%9}, {%0,%1,%2,%3};"
                 : "+f"(c.x), "+f"(c.y), "+f"(c.z), "+f"(c.w)
                 : "r"(a0), "r"(a1), "r"(a2), "r"(a3), "r"(b0), "r"(b1));
}

// ---- per-type row-fragment load (returns 8 fp16 cols packed in uint4) ----
__device__ __forceinline__ uint4 load_frag(const float* __restrict__ in, int gr, int c8) {
    uint4 st = make_uint4(0u, 0u, 0u, 0u);
    if (gr < NN) {
        float4 f0 = *reinterpret_cast<const float4*>(in + (size_t)gr * FD + c8);
        float4 f1 = *reinterpret_cast<const float4*>(in + (size_t)gr * FD + c8 + 4);
        __half2 h0 = __floats2half2_rn(f0.x, f0.y);
        __half2 h1 = __floats2half2_rn(f0.z, f0.w);
        __half2 h2 = __floats2half2_rn(f1.x, f1.y);
        __half2 h3 = __floats2half2_rn(f1.z, f1.w);
        st.x = *reinterpret_cast<unsigned*>(&h0);
        st.y = *reinterpret_cast<unsigned*>(&h1);
        st.z = *reinterpret_cast<unsigned*>(&h2);
        st.w = *reinterpret_cast<unsigned*>(&h3);
    }
    return st;
}

__device__ __forceinline__ uint4 load_frag(const __half* __restrict__ in, int gr, int c8) {
    if (gr < NN) return *reinterpret_cast<const uint4*>(in + (size_t)gr * FD + c8);
    return make_uint4(0u, 0u, 0u, 0u);
}

// ---- GEMM: out[i][:] = fp16( norm_src[i] * (in[i][:] @ W) ), tensor cores ----
// Block: 256 thr / 8 warps, 128 rows in 4 chunks of 32; W staged once.
// A staging is DOUBLE-BUFFERED via register prefetch: next chunk's global
// loads issue before this chunk's MMA phase, overlapping DRAM with compute.
template <typename T>
__global__ __launch_bounds__(256) void gemm_k(const T* __restrict__ in,
                                              __half* __restrict__ out) {
    __shared__ __half sA[32 * SA_STRIDE];
    __shared__ __half sW[FD * SW_STRIDE];
    const int tid = threadIdx.x;
    const int blk0 = blockIdx.x * ROWS_PER_BLK;

    // stage W (fp16, already packed): 128 rows x 128 cols
    for (int i = tid; i < FD * 16; i += 256) {
        int r = i >> 4;
        int c8 = (i & 15) << 3;
        uint4 v = *reinterpret_cast<const uint4*>(g_Wh + r * FD + c8);
        *reinterpret_cast<uint4*>(&sW[r * SW_STRIDE + c8]) = v;
    }

    // per-thread A staging coords (2 fragments of 8 cols)
    const int r0s = tid >> 4;                 // iter 0: rows 0..15
    const int c0s = (tid & 15) << 3;
    const int r1s = (tid + 256) >> 4;         // iter 1: rows 16..31
    const int c1s = c0s;

    const int lane = tid & 31;
    const int wid = tid >> 5;
    const int m0 = (wid & 1) << 4;      // 0 or 16
    const int n0 = (wid >> 1) << 5;     // 0,32,64,96
    const int lm = lane >> 3;           // ldmatrix matrix id
    const int lr = lane & 7;            // row within matrix
    const int arow = m0 + ((lm & 1) << 3) + lr;
    const int koff = (lm >> 1) << 3;

    // prologue: prefetch chunk 0
    uint4 pre0 = load_frag(in, blk0 + r0s, c0s);
    uint4 pre1 = load_frag(in, blk0 + r1s, c1s);

#pragma unroll
    for (int chunk = 0; chunk < 4; chunk++) {
        const int row0 = blk0 + chunk * 32;
        __syncthreads();   // sA free (prev readers done); also covers W stage
        *reinterpret_cast<uint4*>(&sA[r0s * SA_STRIDE + c0s]) = pre0;
        *reinterpret_cast<uint4*>(&sA[r1s * SA_STRIDE + c1s]) = pre1;
        if (chunk < 3) {   // prefetch next chunk; overlaps with MMA below
            pre0 = load_frag(in, row0 + 32 + r0s, c0s);
            pre1 = load_frag(in, row0 + 32 + r1s, c1s);
        }
        __syncthreads();

        float4 c[4];
#pragma unroll
        for (int j = 0; j < 4; j++) c[j] = make_float4(0.f, 0.f, 0.f, 0.f);

#pragma unroll
        for (int ks = 0; ks < 8; ks++) {
            int k0 = ks << 4;
            unsigned a0, a1, a2, a3;
            ldsm_x4(a0, a1, a2, a3, smem_u32(&sA[arow * SA_STRIDE + k0 + koff]));
#pragma unroll
            for (int j = 0; j < 2; j++) {
                int n = n0 + (j << 4);
                unsigned b0, b1, b2, b3;
                ldsm_x4_t(b0, b1, b2, b3,
                          smem_u32(&sW[(k0 + ((lm & 1) << 3) + lr) * SW_STRIDE + n + koff]));
                mma16816(c[2 * j],     a0, a1, a2, a3, b0, b1);
                mma16816(c[2 * j + 1], a0, a1, a2, a3, b2, b3);
            }
        }

        // epilogue: scale by norm_src, convert fp16, store
        const int rA = row0 + m0 + (lane >> 2);
        const int rB = rA + 8;
        float nsA = (rA < NN) ? g_nsrc[rA] : 0.f;
        float nsB = (rB < NN) ? g_nsrc[rB] : 0.f;
#pragma unroll
        for (int j = 0; j < 4; j++) {
            int col = n0 + (j << 3) + ((lane & 3) << 1);
            if (rA < NN) {
                __half2 h = __floats2half2_rn(c[j].x * nsA, c[j].y * nsA);
                *reinterpret_cast<__half2*>(out + (size_t)rA * FD + col) = h;
            }
            if (rB < NN) {
                __half2 h = __floats2half2_rn(c[j].z * nsB, c[j].w * nsB);
                *reinterpret_cast<__half2*>(out + (size_t)rB * FD + col) = h;
            }
        }
    }
}

// ---- warp-per-node CSR accumulate over fp16 rows (fp32 accum), unroll-4 ----
__device__ __forceinline__ float4 csr_accum(int node, int lane) {
    int beg = g_rowptr[node];
    int end = g_rowptr[node + 1];
    float4 acc = make_float4(0.f, 0.f, 0.f, 0.f);
    int j = beg;
    for (; j + 4 <= end; j += 4) {
        int s0 = __ldg(g_csr + j);
        int s1 = __ldg(g_csr + j + 1);
        int s2 = __ldg(g_csr + j + 2);
        int s3 = __ldg(g_csr + j + 3);
        uint2 u0 = *reinterpret_cast<const uint2*>(g_hh + (size_t)s0 * FD + lane * 4);
        uint2 u1 = *reinterpret_cast<const uint2*>(g_hh + (size_t)s1 * FD + lane * 4);
        uint2 u2 = *reinterpret_cast<const uint2*>(g_hh + (size_t)s2 * FD + lane * 4);
        uint2 u3 = *reinterpret_cast<const uint2*>(g_hh + (size_t)s3 * FD + lane * 4);
        float2 a0 = __half22float2(*reinterpret_cast<__half2*>(&u0.x));
        float2 b0 = __half22float2(*reinterpret_cast<__half2*>(&u0.y));
        float2 a1 = __half22float2(*reinterpret_cast<__half2*>(&u1.x));
        float2 b1 = __half22float2(*reinterpret_cast<__half2*>(&u1.y));
        float2 a2 = __half22float2(*reinterpret_cast<__half2*>(&u2.x));
        float2 b2 = __half22float2(*reinterpret_cast<__half2*>(&u2.y));
        float2 a3 = __half22float2(*reinterpret_cast<__half2*>(&u3.x));
        float2 b3 = __half22float2(*reinterpret_cast<__half2*>(&u3.y));
        acc.x += (a0.x + a1.x) + (a2.x + a3.x);
        acc.y += (a0.y + a1.y) + (a2.y + a3.y);
        acc.z += (b0.x + b1.x) + (b2.x + b3.x);
        acc.w += (b0.y + b1.y) + (b2.y + b3.y);
    }
    for (; j < end; j++) {
        int s = __ldg(g_csr + j);
        uint2 u = *reinterpret_cast<const uint2*>(g_hh + (size_t)s * FD + lane * 4);
        float2 a = __half22float2(*reinterpret_cast<__half2*>(&u.x));
        float2 b = __half22float2(*reinterpret_cast<__half2*>(&u.y));
        acc.x += a.x; acc.y += a.y; acc.z += b.x; acc.w += b.y;
    }
    return acc;
}

// ---- layer 1 aggregate, fused epilogue: z = fp16(relu(agg*nd + b1)) ----
__global__ __launch_bounds__(256) void gather1_k(const float* __restrict__ b1) {
    int w = (blockIdx.x * 256 + threadIdx.x) >> 5;
    if (w >= NN) return;
    int lane = threadIdx.x & 31;
    float4 acc = csr_accum(w, lane);
    float nd = g_ndst[w];
    float4 b = __ldg(reinterpret_cast<const float4*>(b1 + lane * 4));
    float ox = fmaxf(fmaf(acc.x, nd, b.x), 0.f);
    float oy = fmaxf(fmaf(acc.y, nd, b.y), 0.f);
    float oz = fmaxf(fmaf(acc.z, nd, b.z), 0.f);
    float ow = fmaxf(fmaf(acc.w, nd, b.w), 0.f);
    __half2 h01 = __floats2half2_rn(ox, oy);
    __half2 h23 = __floats2half2_rn(oz, ow);
    uint2 st;
    st.x = *reinterpret_cast<unsigned*>(&h01);
    st.y = *reinterpret_cast<unsigned*>(&h23);
    *reinterpret_cast<uint2*>(g_zh + (size_t)w * FD + lane * 4) = st;
}

// ---- layer 2 aggregate, fused link-predictor projection: a[i], c[i] ----
__global__ __launch_bounds__(256) void gather2_k(const float* __restrict__ b2,
                                                 const float* __restrict__ Wp) {
    int w = (blockIdx.x * 256 + threadIdx.x) >> 5;
    if (w >= NN) return;
    int lane = threadIdx.x & 31;
    float4 acc = csr_accum(w, lane);
    float nd = g_ndst[w];
    float4 b  = __ldg(reinterpret_cast<const float4*>(b2 + lane * 4));
    float4 w1 = __ldg(reinterpret_cast<const float4*>(Wp + lane * 4));
    float4 w2 = __ldg(reinterpret_cast<const float4*>(Wp + FD + lane * 4));
    float hx = fmaf(acc.x, nd, b.x);
    float hy = fmaf(acc.y, nd, b.y);
    float hz = fmaf(acc.z, nd, b.z);
    float hw = fmaf(acc.w, nd, b.w);
    float av = hx * w1.x + hy * w1.y + hz * w1.z + hw * w1.w;
    float cv = hx * w2.x + hy * w2.y + hz * w2.z + hw * w2.w;
#pragma unroll
    for (int off = 16; off > 0; off >>= 1) {
        av += __shfl_xor_sync(0xffffffffu, av, off);
        cv += __shfl_xor_sync(0xffffffffu, cv, off);
    }
    if (lane == 0) { g_a[w] = av; g_c[w] = cv; }
}

// ---- final per-edge score: sigmoid(a[src] + c[dst] + bp) ----
__global__ void edgescore_k(const int* __restrict__ src, const int* __restrict__ dst,
                            const float* __restrict__ bp, float* __restrict__ out) {
    int e = blockIdx.x * blockDim.x + threadIdx.x;
    if (e < NE) {
        float z = g_a[__ldg(src + e)] + g_c[__ldg(dst + e)] + __ldg(bp);
        out[e] = 1.0f / (1.0f + expf(-z));
    }
}

extern "C" void kernel_launch(void* const* d_in, const int* in_sizes, int n_in,
                              void* d_out, int out_size) {
    (void)in_sizes; (void)n_in; (void)out_size;
    const float* x  = (const float*)d_in[0];
    const float* W1 = (const float*)d_in[1];
    const float* b1 = (const float*)d_in[2];
    const float* W2 = (const float*)d_in[3];
    const float* b2 = (const float*)d_in[4];
    const float* Wp = (const float*)d_in[5];
    const float* bp = (const float*)d_in[6];
    const int* src  = (const int*)d_in[7];
    const int* dst  = (const int*)d_in[8];
    float* out = (float*)d_out;

    void *p_hh, *p_zh, *p_di, *p_do;
    cudaGetSymbolAddress(&p_hh, g_hh);
    cudaGetSymbolAddress(&p_zh, g_zh);
    cudaGetSymbolAddress(&p_di, g_degin);
    cudaGetSymbolAddress(&p_do, g_degout);

    cudaMemsetAsync(p_di, 0, sizeof(int) * NN);
    cudaMemsetAsync(p_do, 0, sizeof(int) * NN);

    // degrees + norms, then GEMM1 EARLY so ncu (-s 5 -c 1) profiles gemm_k
    count_k<<<(NE + 255) / 256, 256>>>(src, dst);
    norm_k<<<(NN + 255) / 256, 256>>>();
    packW_k<<<(FD * FD + 255) / 256, 256>>>(W1);
    gemm_k<float><<<(NN + ROWS_PER_BLK - 1) / ROWS_PER_BLK, 256>>>(x, (__half*)p_hh);

    // CSR (dst-bucketed) build
    blocksum_k<<<NB, 256>>>();
    scanbsum_k<<<1, 512>>>();
    rowptr_k<<<NB, 256>>>();
    fill_k<<<(NE + 255) / 256, 256>>>(src, dst);

    // Layer 1 aggregate: z = fp16(relu(agg1 * norm_dst + b1))
    gather1_k<<<(NN * 32 + 255) / 256, 256>>>(b1);

    // Layer 2: h = fp16((z @ W2) * norm_src) ; fused gather -> per-node a, c
    packW_k<<<(FD * FD + 255) / 256, 256>>>(W2);
    gemm_k<__half><<<(NN + ROWS_PER_BLK - 1) / ROWS_PER_BLK, 256>>>((const __half*)p_zh, (__half*)p_hh);
    gather2_k<<<(NN * 32 + 255) / 256, 256>>>(b2, Wp);

    // Per-edge score
    edgescore_k<<<(NE + 255) / 256, 256>>>(src, dst, bp, out);
}